// round 6
// baseline (speedup 1.0000x reference)
#include <cuda_runtime.h>

// Density loss via exact KNN (k=16, self included) on [8, 2048, 3] clouds.
//
// Strategy: per (tensor,batch) block, sort the 2048 points by x inside the
// block (bitonic on (sortable_x, idx) u64 keys), then each warp scans
// candidate batches of 16 OUTWARD from its own 32 consecutive sorted points.
//   - Exact early exit: if (x_edge - xi)^2 > t for all lanes (t = current
//     16th-smallest distance), no farther candidate in that direction can
//     ever enter the top-16 (t only decreases). Break.
//   - Warp-ballot screen: the 206-FMNMX sort/merge network runs only when
//     some lane's batch-min beats t. Outward order makes t converge fast.
// Final reduction + MSE folded in via last-block counter (single kernel).

#define B 8
#define N 2048
#define KNN 16
#define THREADS 256
#define SEGS (N / THREADS)                   // 8
#define BLOCKS_PER_TENSOR (B * SEGS)         // 64
#define TOTAL_BLOCKS (2 * BLOCKS_PER_TENSOR) // 128

__device__ float g_partial[TOTAL_BLOCKS];
__device__ int g_count = 0;

// compare-exchange: x <- min, y <- max
#define CE(x, y) { float _lo = fminf((x), (y)); (y) = fmaxf((x), (y)); (x) = _lo; }

// Sort 16 candidates (Batcher, 63 CE), keep 16 smallest of (a ∪ c) via
// bitonic min-step, restore sortedness of a with a 32-CE bitonic cleanup.
__device__ __forceinline__ void merge_batch(float (&a)[KNN], float (&c)[KNN], float& t) {
    // sort4 (0-3)
    CE(c[0], c[1]) CE(c[2], c[3]) CE(c[0], c[2]) CE(c[1], c[3]) CE(c[1], c[2])
    // sort4 (4-7)
    CE(c[4], c[5]) CE(c[6], c[7]) CE(c[4], c[6]) CE(c[5], c[7]) CE(c[5], c[6])
    // merge8 (0-7)
    CE(c[0], c[4]) CE(c[2], c[6]) CE(c[2], c[4])
    CE(c[1], c[5]) CE(c[3], c[7]) CE(c[3], c[5])
    CE(c[1], c[2]) CE(c[3], c[4]) CE(c[5], c[6])
    // sort4 (8-11)
    CE(c[8], c[9]) CE(c[10], c[11]) CE(c[8], c[10]) CE(c[9], c[11]) CE(c[9], c[10])
    // sort4 (12-15)
    CE(c[12], c[13]) CE(c[14], c[15]) CE(c[12], c[14]) CE(c[13], c[15]) CE(c[13], c[14])
    // merge8 (8-15)
    CE(c[8], c[12]) CE(c[10], c[14]) CE(c[10], c[12])
    CE(c[9], c[13]) CE(c[11], c[15]) CE(c[11], c[13])
    CE(c[9], c[10]) CE(c[11], c[12]) CE(c[13], c[14])
    // merge16: evens
    CE(c[0], c[8])  CE(c[4], c[12]) CE(c[4], c[8])
    CE(c[2], c[10]) CE(c[6], c[14]) CE(c[6], c[10])
    CE(c[2], c[4])  CE(c[6], c[8])  CE(c[10], c[12])
    // merge16: odds
    CE(c[1], c[9])  CE(c[5], c[13]) CE(c[5], c[9])
    CE(c[3], c[11]) CE(c[7], c[15]) CE(c[7], c[11])
    CE(c[3], c[5])  CE(c[7], c[9])  CE(c[11], c[13])
    // merge16: final layer
    CE(c[1], c[2]) CE(c[3], c[4]) CE(c[5], c[6]) CE(c[7], c[8])
    CE(c[9], c[10]) CE(c[11], c[12]) CE(c[13], c[14])

    // keep lowest 16 of (a asc, c asc)
#pragma unroll
    for (int q = 0; q < KNN; ++q) a[q] = fminf(a[q], c[15 - q]);

    // a is bitonic: 4-stage bitonic cleanup (32 CE)
#pragma unroll
    for (int q = 0; q < 8; ++q) CE(a[q], a[q + 8])
    CE(a[0], a[4]) CE(a[1], a[5]) CE(a[2], a[6]) CE(a[3], a[7])
    CE(a[8], a[12]) CE(a[9], a[13]) CE(a[10], a[14]) CE(a[11], a[15])
    CE(a[0], a[2]) CE(a[1], a[3]) CE(a[4], a[6]) CE(a[5], a[7])
    CE(a[8], a[10]) CE(a[9], a[11]) CE(a[12], a[14]) CE(a[13], a[15])
    CE(a[0], a[1]) CE(a[2], a[3]) CE(a[4], a[5]) CE(a[6], a[7])
    CE(a[8], a[9]) CE(a[10], a[11]) CE(a[12], a[13]) CE(a[14], a[15])

    t = a[15];
}

__global__ __launch_bounds__(THREADS)
void knn_density_kernel(const float* __restrict__ seed,
                        const float* __restrict__ gt_s,
                        float* __restrict__ out) {
    __shared__ unsigned long long key[N];  // 16 KB; reused as scratch later
    __shared__ float4 pts[N];              // 32 KB (sorted by x)

    const int bx     = blockIdx.x;
    const int seg    = bx % SEGS;
    const int batch  = (bx / SEGS) % B;
    const int tensor = bx / BLOCKS_PER_TENSOR;
    const int tid    = threadIdx.x;

    const float* __restrict__ src =
        (tensor == 0 ? seed : gt_s) + (size_t)batch * N * 3;

    // ---- build (sortable_x, idx) keys ----
    for (int i = tid; i < N; i += THREADS) {
        unsigned u = __float_as_uint(src[3 * i]);
        u = (u & 0x80000000u) ? ~u : (u | 0x80000000u);
        key[i] = ((unsigned long long)u << 32) | (unsigned)i;
    }

    // ---- bitonic sort (ascending x) ----
    for (int k = 2; k <= N; k <<= 1) {
        for (int j = k >> 1; j > 0; j >>= 1) {
            __syncthreads();
            for (int i = tid; i < N; i += THREADS) {
                int l = i ^ j;
                if (l > i) {
                    unsigned long long u0 = key[i], u1 = key[l];
                    if ((u0 > u1) == ((i & k) == 0)) { key[i] = u1; key[l] = u0; }
                }
            }
        }
    }
    __syncthreads();

    // ---- gather sorted points with |p|^2 ----
    for (int i = tid; i < N; i += THREADS) {
        int idx = (int)(key[i] & 0xffffffffu);
        float x = src[3 * idx], y = src[3 * idx + 1], z = src[3 * idx + 2];
        pts[i] = make_float4(x, y, z, x * x + y * y + z * z);
    }
    __syncthreads();

    // ---- per-point top-16 scan ----
    const int warp      = tid >> 5;
    const int warp_base = seg * THREADS + warp * 32;
    const int myp       = warp_base + (tid & 31);

    const float4 xi = pts[myp];
    const float xix = xi.x;
    const float ai  = xi.w;
    const float mx  = -2.0f * xi.x;
    const float my  = -2.0f * xi.y;
    const float mz  = -2.0f * xi.z;

    float a[KNN];
#pragma unroll
    for (int q = 0; q < KNN; ++q) a[q] = 3.4e38f;
    float t = 3.4e38f;

    // right scan (includes own batches)
    for (int base = warp_base; base < N; base += 16) {
        float dxs = pts[base].x - xix;
        if (__all_sync(0xffffffffu, (dxs > 0.0f) && (dxs * dxs > t))) break;
        float c[16];
#pragma unroll
        for (int q = 0; q < 16; ++q) {
            float4 s = pts[base + q];
            float d = ai + s.w;
            d = fmaf(mx, s.x, d);
            d = fmaf(my, s.y, d);
            d = fmaf(mz, s.z, d);
            c[q] = d;
        }
        float m0 = fminf(fminf(fminf(c[0], c[1]), fminf(c[2], c[3])),
                         fminf(fminf(c[4], c[5]), fminf(c[6], c[7])));
        float m1 = fminf(fminf(fminf(c[8], c[9]), fminf(c[10], c[11])),
                         fminf(fminf(c[12], c[13]), fminf(c[14], c[15])));
        if (__ballot_sync(0xffffffffu, fminf(m0, m1) < t))
            merge_batch(a, c, t);
    }

    // left scan
    for (int base = warp_base - 16; base >= 0; base -= 16) {
        float dxs = xix - pts[base + 15].x;
        if (__all_sync(0xffffffffu, (dxs > 0.0f) && (dxs * dxs > t))) break;
        float c[16];
#pragma unroll
        for (int q = 0; q < 16; ++q) {
            float4 s = pts[base + q];
            float d = ai + s.w;
            d = fmaf(mx, s.x, d);
            d = fmaf(my, s.y, d);
            d = fmaf(mz, s.z, d);
            c[q] = d;
        }
        float m0 = fminf(fminf(fminf(c[0], c[1]), fminf(c[2], c[3])),
                         fminf(fminf(c[4], c[5]), fminf(c[6], c[7])));
        float m1 = fminf(fminf(fminf(c[8], c[9]), fminf(c[10], c[11])),
                         fminf(fminf(c[12], c[13]), fminf(c[14], c[15])));
        if (__ballot_sync(0xffffffffu, fminf(m0, m1) < t))
            merge_batch(a, c, t);
    }

    // per-point mean of 16 nearest
    float s16 = 0.0f;
#pragma unroll
    for (int q = 0; q < KNN; ++q) s16 += a[q];
    float point_mean = s16 * (1.0f / KNN);

    // ---- block reduction (smem aliased onto dead key buffer) ----
    float* red = reinterpret_cast<float*>(key);       // [0..255]
    float* dd  = reinterpret_cast<float*>(key) + 256; // [256..271]
    int* plast = reinterpret_cast<int*>(reinterpret_cast<float*>(key) + 272);

    __syncthreads();
    red[tid] = point_mean;
    __syncthreads();
#pragma unroll
    for (int stride = THREADS / 2; stride > 0; stride >>= 1) {
        if (tid < stride) red[tid] += red[tid + stride];
        __syncthreads();
    }
    if (tid == 0) g_partial[bx] = red[0];

    // ---- last-block finalize ----
    __threadfence();
    if (tid == 0) *plast = (atomicAdd(&g_count, 1) == TOTAL_BLOCKS - 1);
    __syncthreads();
    if (*plast) {
        float v = (tid < TOTAL_BLOCKS) ? __ldcg(&g_partial[tid]) : 0.0f;
        __syncthreads();
        red[tid] = v;
        __syncthreads();
        if (tid < 2 * B) {
            float s = 0.0f;
#pragma unroll
            for (int c2 = 0; c2 < SEGS; ++c2) s += red[tid * SEGS + c2];
            dd[tid] = s * (1.0f / N);
        }
        __syncthreads();
        if (tid == 0) {
            float loss = 0.0f;
#pragma unroll
            for (int b = 0; b < B; ++b) {
                float df = dd[b] - dd[B + b];
                loss += df * df;
            }
            out[0] = loss * (1.0f / B);
            g_count = 0;  // reset for next graph replay
        }
    }
}

extern "C" void kernel_launch(void* const* d_in, const int* in_sizes, int n_in,
                              void* d_out, int out_size) {
    const float* seed = (const float*)d_in[0];
    const float* gt_s = (const float*)d_in[1];
    float* out = (float*)d_out;

    knn_density_kernel<<<TOTAL_BLOCKS, THREADS>>>(seed, gt_s, out);
}